// round 1
// baseline (speedup 1.0000x reference)
#include <cuda_runtime.h>
#include <math.h>
#include <stdint.h>
#include <stddef.h>

// Problem constants
#define NB 2
#define NS 2048
#define NC 2048
#define ND 128
#define NH 16
#define NM (NB * NS)       // 4096 rows
#define NBH (NB * NH)      // 32 batch-heads
#define RMS_EPS 1.1920928955078125e-07f
#define SM_SCALE 0.08838834764831844f  // 1/sqrt(128)

// GEMM tiling
#define TBM 128
#define TBN 128
#define TBK 16

// ---------------- scratch (allocation-free: device globals) ----------------
__device__ float g_q[(size_t)NM * NC];
__device__ float g_k[(size_t)NM * NC];
__device__ float g_v[(size_t)NM * NC];
__device__ float g_ctx[(size_t)NM * NC];
__device__ float g_sc[(size_t)NBH * NS * NS];  // 512 MB scores/probs

// ---------------- shared GEMM tile bodies ----------------
// NT: Out[m,n] = sum_k A[m,k] * B[n,k] (+ bias[n]); pointers pre-offset to tile.
__device__ __forceinline__ void gemm_nt_tile(
    const float* __restrict__ A, int lda,
    const float* __restrict__ Bm, int ldb,
    const float* __restrict__ bias,   // may be nullptr; pre-offset to bn
    float* __restrict__ Out, int ldo,
    int K)
{
    __shared__ float As[TBK][TBM];
    __shared__ float Bs[TBK][TBN];
    const int tid = threadIdx.x;           // 256 threads
    const int tx = tid & 15;
    const int ty = tid >> 4;

    float acc[8][8];
    #pragma unroll
    for (int i = 0; i < 8; i++)
        #pragma unroll
        for (int j = 0; j < 8; j++) acc[i][j] = 0.0f;

    for (int k0 = 0; k0 < K; k0 += TBK) {
        #pragma unroll
        for (int i = 0; i < 2; i++) {
            int f = tid + i * 256;          // 0..511
            int r = f >> 2;                 // 0..127
            int kc = (f & 3) << 2;          // 0,4,8,12
            float4 a = *(const float4*)(A + (size_t)r * lda + k0 + kc);
            As[kc + 0][r] = a.x; As[kc + 1][r] = a.y;
            As[kc + 2][r] = a.z; As[kc + 3][r] = a.w;
            float4 w = *(const float4*)(Bm + (size_t)r * ldb + k0 + kc);
            Bs[kc + 0][r] = w.x; Bs[kc + 1][r] = w.y;
            Bs[kc + 2][r] = w.z; Bs[kc + 3][r] = w.w;
        }
        __syncthreads();
        #pragma unroll
        for (int kk = 0; kk < TBK; kk++) {
            float ra[8], rb[8];
            *(float4*)(ra)     = *(const float4*)&As[kk][ty * 8];
            *(float4*)(ra + 4) = *(const float4*)&As[kk][ty * 8 + 4];
            *(float4*)(rb)     = *(const float4*)&Bs[kk][tx * 8];
            *(float4*)(rb + 4) = *(const float4*)&Bs[kk][tx * 8 + 4];
            #pragma unroll
            for (int i = 0; i < 8; i++)
                #pragma unroll
                for (int j = 0; j < 8; j++)
                    acc[i][j] += ra[i] * rb[j];
        }
        __syncthreads();
    }

    #pragma unroll
    for (int i = 0; i < 8; i++) {
        int m = ty * 8 + i;
        #pragma unroll
        for (int j = 0; j < 8; j += 4) {
            int n = tx * 8 + j;
            float4 o;
            if (bias) {
                float4 bvv = *(const float4*)(bias + n);
                o.x = acc[i][j]     + bvv.x;
                o.y = acc[i][j + 1] + bvv.y;
                o.z = acc[i][j + 2] + bvv.z;
                o.w = acc[i][j + 3] + bvv.w;
            } else {
                o.x = acc[i][j];     o.y = acc[i][j + 1];
                o.z = acc[i][j + 2]; o.w = acc[i][j + 3];
            }
            *(float4*)(Out + (size_t)m * ldo + n) = o;
        }
    }
}

// NN: Out[m,n] = sum_k A[m,k] * B[k,n]; pointers pre-offset to tile.
__device__ __forceinline__ void gemm_nn_tile(
    const float* __restrict__ A, int lda,
    const float* __restrict__ Bm, int ldb,
    float* __restrict__ Out, int ldo,
    int K)
{
    __shared__ float As[TBK][TBM];
    __shared__ float Bs[TBK][TBN];
    const int tid = threadIdx.x;
    const int tx = tid & 15;
    const int ty = tid >> 4;

    float acc[8][8];
    #pragma unroll
    for (int i = 0; i < 8; i++)
        #pragma unroll
        for (int j = 0; j < 8; j++) acc[i][j] = 0.0f;

    for (int k0 = 0; k0 < K; k0 += TBK) {
        #pragma unroll
        for (int i = 0; i < 2; i++) {
            int f = tid + i * 256;
            int r = f >> 2;
            int kc = (f & 3) << 2;
            float4 a = *(const float4*)(A + (size_t)r * lda + k0 + kc);
            As[kc + 0][r] = a.x; As[kc + 1][r] = a.y;
            As[kc + 2][r] = a.z; As[kc + 3][r] = a.w;
            int kr = f >> 5;                // 0..15
            int c  = (f & 31) << 2;         // 0..124
            float4 w = *(const float4*)(Bm + (size_t)(k0 + kr) * ldb + c);
            *(float4*)&Bs[kr][c] = w;
        }
        __syncthreads();
        #pragma unroll
        for (int kk = 0; kk < TBK; kk++) {
            float ra[8], rb[8];
            *(float4*)(ra)     = *(const float4*)&As[kk][ty * 8];
            *(float4*)(ra + 4) = *(const float4*)&As[kk][ty * 8 + 4];
            *(float4*)(rb)     = *(const float4*)&Bs[kk][tx * 8];
            *(float4*)(rb + 4) = *(const float4*)&Bs[kk][tx * 8 + 4];
            #pragma unroll
            for (int i = 0; i < 8; i++)
                #pragma unroll
                for (int j = 0; j < 8; j++)
                    acc[i][j] += ra[i] * rb[j];
        }
        __syncthreads();
    }

    #pragma unroll
    for (int i = 0; i < 8; i++) {
        int m = ty * 8 + i;
        #pragma unroll
        for (int j = 0; j < 8; j += 4) {
            int n = tx * 8 + j;
            float4 o;
            o.x = acc[i][j];     o.y = acc[i][j + 1];
            o.z = acc[i][j + 2]; o.w = acc[i][j + 3];
            *(float4*)(Out + (size_t)m * ldo + n) = o;
        }
    }
}

// ---------------- kernels ----------------
// Projections: Out[M=4096, 2048] = A[4096,2048] @ W[2048,2048]^T + bias
__global__ __launch_bounds__(256) void gemm_proj(
    const float* __restrict__ A, const float* __restrict__ W,
    const float* __restrict__ bias, float* __restrict__ Out)
{
    size_t bm = (size_t)blockIdx.y * TBM;
    size_t bn = (size_t)blockIdx.x * TBN;
    gemm_nt_tile(A + bm * NC, NC, W + bn * NC, NC, bias + bn,
                 Out + bm * NC + bn, NC, NC);
}

// Per-head RMSNorm + RoPE, in-place on g_q / g_k. One warp per (row, head).
__global__ __launch_bounds__(256) void rmsnorm_rope(
    const float* __restrict__ rope,
    const float* __restrict__ gq, const float* __restrict__ gk)
{
    int warp = blockIdx.x * 8 + (threadIdx.x >> 5);
    int lane = threadIdx.x & 31;
    int m = warp >> 4;          // 0..4095
    int h = warp & 15;
    int s = m & (NS - 1);

    float* qr = g_q + (size_t)m * NC + h * ND;
    float* kr = g_k + (size_t)m * NC + h * ND;
    const float* rp = rope + (size_t)s * (ND / 2) * 4;
    int d = lane * 4;

    float4 xq = *(float4*)(qr + d);
    float4 xk = *(float4*)(kr + d);
    float ssq = xq.x * xq.x + xq.y * xq.y + xq.z * xq.z + xq.w * xq.w;
    float ssk = xk.x * xk.x + xk.y * xk.y + xk.z * xk.z + xk.w * xk.w;
    #pragma unroll
    for (int o = 16; o; o >>= 1) {
        ssq += __shfl_xor_sync(0xffffffffu, ssq, o);
        ssk += __shfl_xor_sync(0xffffffffu, ssk, o);
    }
    float rq = rsqrtf(ssq * (1.0f / ND) + RMS_EPS);
    float rk = rsqrtf(ssk * (1.0f / ND) + RMS_EPS);

    float4 gqv = *(const float4*)(gq + d);
    float4 gkv = *(const float4*)(gk + d);
    xq.x *= rq * gqv.x; xq.y *= rq * gqv.y; xq.z *= rq * gqv.z; xq.w *= rq * gqv.w;
    xk.x *= rk * gkv.x; xk.y *= rk * gkv.y; xk.z *= rk * gkv.z; xk.w *= rk * gkv.w;

    // rope pairs: d2a = 2*lane (covers elems d,d+1), d2b = 2*lane+1 (d+2,d+3)
    float4 r0 = *(const float4*)(rp + (size_t)(2 * lane) * 4);
    float4 r1 = *(const float4*)(rp + (size_t)(2 * lane + 1) * 4);
    float4 oq, ok;
    oq.x = r0.x * xq.x + r0.y * xq.y;  oq.y = r0.z * xq.x + r0.w * xq.y;
    oq.z = r1.x * xq.z + r1.y * xq.w;  oq.w = r1.z * xq.z + r1.w * xq.w;
    ok.x = r0.x * xk.x + r0.y * xk.y;  ok.y = r0.z * xk.x + r0.w * xk.y;
    ok.z = r1.x * xk.z + r1.y * xk.w;  ok.w = r1.z * xk.z + r1.w * xk.w;

    *(float4*)(qr + d) = oq;
    *(float4*)(kr + d) = ok;
}

// Scores: for each (b,h): sc[2048,2048] = Qh @ Kh^T  (raw, scale applied in softmax)
__global__ __launch_bounds__(256) void gemm_scores_k()
{
    int bh = blockIdx.z, b = bh >> 4, h = bh & 15;
    const float* A  = g_q + ((size_t)b * NS + (size_t)blockIdx.y * TBM) * NC + h * ND;
    const float* Bp = g_k + ((size_t)b * NS + (size_t)blockIdx.x * TBN) * NC + h * ND;
    float* Out = g_sc + (size_t)bh * NS * NS
                      + (size_t)blockIdx.y * TBM * NS + (size_t)blockIdx.x * TBN;
    gemm_nt_tile(A, NC, Bp, NC, nullptr, Out, NS, ND);
}

// Row softmax over 2048 keys (scale folded into exp argument).
__global__ __launch_bounds__(256) void softmax_rows()
{
    float* p = g_sc + (size_t)blockIdx.x * NS;
    int tid = threadIdx.x;
    __shared__ float sh[8];

    float4 v0 = ((const float4*)p)[tid];
    float4 v1 = ((const float4*)p)[tid + 256];
    float mx = fmaxf(fmaxf(fmaxf(v0.x, v0.y), fmaxf(v0.z, v0.w)),
                     fmaxf(fmaxf(v1.x, v1.y), fmaxf(v1.z, v1.w)));
    #pragma unroll
    for (int o = 16; o; o >>= 1) mx = fmaxf(mx, __shfl_xor_sync(0xffffffffu, mx, o));
    if ((tid & 31) == 0) sh[tid >> 5] = mx;
    __syncthreads();
    if (tid < 32) {
        float t = sh[tid & 7];
        #pragma unroll
        for (int o = 4; o; o >>= 1) t = fmaxf(t, __shfl_xor_sync(0xffffffffu, t, o));
        if (tid == 0) sh[0] = t;
    }
    __syncthreads();
    mx = sh[0];
    __syncthreads();  // before sh reuse

    v0.x = __expf((v0.x - mx) * SM_SCALE); v0.y = __expf((v0.y - mx) * SM_SCALE);
    v0.z = __expf((v0.z - mx) * SM_SCALE); v0.w = __expf((v0.w - mx) * SM_SCALE);
    v1.x = __expf((v1.x - mx) * SM_SCALE); v1.y = __expf((v1.y - mx) * SM_SCALE);
    v1.z = __expf((v1.z - mx) * SM_SCALE); v1.w = __expf((v1.w - mx) * SM_SCALE);
    float sum = v0.x + v0.y + v0.z + v0.w + v1.x + v1.y + v1.z + v1.w;
    #pragma unroll
    for (int o = 16; o; o >>= 1) sum += __shfl_xor_sync(0xffffffffu, sum, o);
    if ((tid & 31) == 0) sh[tid >> 5] = sum;
    __syncthreads();
    if (tid < 32) {
        float t = sh[tid & 7];
        #pragma unroll
        for (int o = 4; o; o >>= 1) t += __shfl_xor_sync(0xffffffffu, t, o);
        if (tid == 0) sh[0] = t;
    }
    __syncthreads();
    float inv = 1.0f / sh[0];
    v0.x *= inv; v0.y *= inv; v0.z *= inv; v0.w *= inv;
    v1.x *= inv; v1.y *= inv; v1.z *= inv; v1.w *= inv;
    ((float4*)p)[tid] = v0;
    ((float4*)p)[tid + 256] = v1;
}

// PV: for each (b,h): ctx_h[2048,128] = P[2048,2048] @ V_h[2048,128]
__global__ __launch_bounds__(256) void gemm_pv_k()
{
    int bh = blockIdx.z, b = bh >> 4, h = bh & 15;
    const float* A  = g_sc + (size_t)bh * NS * NS + (size_t)blockIdx.y * TBM * NS;
    const float* Bp = g_v + (size_t)b * NS * NC + h * ND;
    float* Out = g_ctx + ((size_t)b * NS + (size_t)blockIdx.y * TBM) * NC + h * ND;
    gemm_nn_tile(A, NS, Bp, NC, Out, NC, NS);
}

// ---------------- launch ----------------
extern "C" void kernel_launch(void* const* d_in, const int* in_sizes, int n_in,
                              void* d_out, int out_size)
{
    const float* x    = (const float*)d_in[0];
    const float* rope = (const float*)d_in[1];
    const float* Wq   = (const float*)d_in[2];
    const float* bq   = (const float*)d_in[3];
    const float* Wk   = (const float*)d_in[4];
    const float* bk   = (const float*)d_in[5];
    const float* Wv   = (const float*)d_in[6];
    const float* bv   = (const float*)d_in[7];
    const float* gq   = (const float*)d_in[8];
    const float* gk   = (const float*)d_in[9];
    const float* Wo   = (const float*)d_in[10];
    const float* bo   = (const float*)d_in[11];
    float* out = (float*)d_out;

    float *qp, *kp, *vp, *ctxp;
    cudaGetSymbolAddress((void**)&qp,   g_q);
    cudaGetSymbolAddress((void**)&kp,   g_k);
    cudaGetSymbolAddress((void**)&vp,   g_v);
    cudaGetSymbolAddress((void**)&ctxp, g_ctx);

    dim3 gProj(NC / TBN, NM / TBM);          // (16, 32)
    gemm_proj<<<gProj, 256>>>(x, Wq, bq, qp);
    gemm_proj<<<gProj, 256>>>(x, Wk, bk, kp);
    gemm_proj<<<gProj, 256>>>(x, Wv, bv, vp);

    rmsnorm_rope<<<(NM * NH) / 8, 256>>>(rope, gq, gk);

    gemm_scores_k<<<dim3(NS / TBN, NS / TBM, NBH), 256>>>();   // (16,16,32)
    softmax_rows<<<NBH * NS, 256>>>();                          // 65536 rows
    gemm_pv_k<<<dim3(1, NS / TBM, NBH), 256>>>();               // (1,16,32)

    gemm_proj<<<gProj, 256>>>(ctxp, Wo, bo, out);
}

// round 3
// speedup vs baseline: 2.3080x; 2.3080x over previous
#include <cuda_runtime.h>
#include <cuda_bf16.h>
#include <math.h>
#include <stdint.h>
#include <stddef.h>

#define NB 2
#define NS 2048
#define NC 2048
#define ND 128
#define NH 16
#define NM (NB * NS)       // 4096
#define NBH (NB * NH)      // 32
#define RMS_EPS 1.1920928955078125e-07f
#define SM_SCALE 0.08838834764831844f

typedef __nv_bfloat16 bf16;

// ---------------- scratch (device globals; no allocation) ----------------
__device__ float g_q[(size_t)NM * NC];
__device__ float g_k[(size_t)NM * NC];
__device__ float g_v[(size_t)NM * NC];
__device__ float g_ctx[(size_t)NM * NC];
__device__ float g_sc[(size_t)NBH * NS * NS];          // 512 MB raw scores

__device__ bf16 g_xh[(size_t)NM * NC],  g_xl[(size_t)NM * NC];
__device__ bf16 g_wqh[(size_t)NC * NC], g_wql[(size_t)NC * NC];
__device__ bf16 g_wkh[(size_t)NC * NC], g_wkl[(size_t)NC * NC];
__device__ bf16 g_wvh[(size_t)NC * NC], g_wvl[(size_t)NC * NC];
__device__ bf16 g_woh[(size_t)NC * NC], g_wol[(size_t)NC * NC];
__device__ bf16 g_qh[(size_t)NM * NC],  g_ql[(size_t)NM * NC];
__device__ bf16 g_kh[(size_t)NM * NC],  g_kl[(size_t)NM * NC];
__device__ bf16 g_vth[(size_t)NB * NC * NS], g_vtl[(size_t)NB * NC * NS];
__device__ bf16 g_ph[(size_t)NBH * NS * NS], g_pl[(size_t)NBH * NS * NS];
__device__ bf16 g_ch[(size_t)NM * NC],  g_cl[(size_t)NM * NC];

// ---------------- PTX helpers (sm_80-era: compile on any sm_103 target) ---
__device__ __forceinline__ uint32_t smem_to_u32(const void* p) {
    uint32_t a;
    asm("{ .reg .u64 t; cvta.to.shared.u64 t, %1; cvt.u32.u64 %0, t; }"
        : "=r"(a) : "l"(p));
    return a;
}
__device__ __forceinline__ void cp_async16(uint32_t dst, const void* src) {
    asm volatile("cp.async.cg.shared.global [%0], [%1], 16;"
                 :: "r"(dst), "l"(src) : "memory");
}
__device__ __forceinline__ void cp_commit() {
    asm volatile("cp.async.commit_group;" ::: "memory");
}
template <int N>
__device__ __forceinline__ void cp_wait() {
    asm volatile("cp.async.wait_group %0;" :: "n"(N) : "memory");
}
__device__ __forceinline__ void ldm_x4(uint32_t (&r)[4], uint32_t addr) {
    asm volatile("ldmatrix.sync.aligned.m8n8.x4.shared.b16 {%0,%1,%2,%3}, [%4];"
                 : "=r"(r[0]), "=r"(r[1]), "=r"(r[2]), "=r"(r[3]) : "r"(addr));
}
__device__ __forceinline__ void mma_bf16(float (&d)[4], const uint32_t (&a)[4],
                                         uint32_t b0, uint32_t b1) {
    asm volatile("mma.sync.aligned.m16n8k16.row.col.f32.bf16.bf16.f32 "
                 "{%0,%1,%2,%3}, {%4,%5,%6,%7}, {%8,%9}, {%0,%1,%2,%3};"
                 : "+f"(d[0]), "+f"(d[1]), "+f"(d[2]), "+f"(d[3])
                 : "r"(a[0]), "r"(a[1]), "r"(a[2]), "r"(a[3]), "r"(b0), "r"(b1));
}

// ---------------- bf16x3 HMMA GEMM (128x128 tile, K-chunk 32) ------------
// smem layout per stage: [Ah | Al | Bh | Bl], each 128 rows x 80B (32 bf16 + 8 pad)
#define KCH 32
#define ROW_BYTES 80
#define TILE_BYTES (128 * ROW_BYTES)        // 10240
#define STAGE_BYTES (4 * TILE_BYTES)        // 40960
#define GEMM_SMEM (2 * STAGE_BYTES)         // 81920

__device__ __forceinline__ void load_tile_async(uint32_t smbase, const bf16* g,
                                                int ld, int k0, int tid) {
    const char* gp = (const char*)(g + k0);
    #pragma unroll
    for (int j = 0; j < 2; j++) {
        int i = tid + j * 256;
        int row = i >> 2;
        int c = i & 3;                       // 16B chunk within the 64B row
        cp_async16(smbase + row * ROW_BYTES + c * 16,
                   gp + (size_t)row * ld * 2 + c * 16);
    }
}

__device__ __forceinline__ void gemm_hmma_tile(
    const bf16* __restrict__ Ah, const bf16* __restrict__ Al, int lda,
    const bf16* __restrict__ Bh, const bf16* __restrict__ Bl, int ldb,
    const float* __restrict__ bias, float* __restrict__ Out, int ldo, int K)
{
    extern __shared__ char sm[];
    uint32_t sb = smem_to_u32(sm);
    const int tid = threadIdx.x;            // 256 threads = 8 warps
    const int lane = tid & 31;
    const int warp = tid >> 5;
    const int wm = warp >> 1;               // 0..3  (rows: wm*32)
    const int wn = warp & 1;                // 0..1  (cols: wn*64)

    float acc[2][8][4];
    #pragma unroll
    for (int mt = 0; mt < 2; mt++)
        #pragma unroll
        for (int nt = 0; nt < 8; nt++)
            #pragma unroll
            for (int j = 0; j < 4; j++) acc[mt][nt][j] = 0.0f;

    const int nch = K / KCH;

    auto load_chunk = [&](int ch, int s) {
        uint32_t base = sb + s * STAGE_BYTES;
        int k0 = ch * KCH;
        load_tile_async(base,                  Ah, lda, k0, tid);
        load_tile_async(base + TILE_BYTES,     Al, lda, k0, tid);
        load_tile_async(base + 2 * TILE_BYTES, Bh, ldb, k0, tid);
        load_tile_async(base + 3 * TILE_BYTES, Bl, ldb, k0, tid);
    };

    load_chunk(0, 0);
    cp_commit();

    for (int ch = 0; ch < nch; ch++) {
        int cur = ch & 1;
        if (ch + 1 < nch) {
            load_chunk(ch + 1, cur ^ 1);
            cp_commit();
            cp_wait<1>();
        } else {
            cp_wait<0>();
        }
        __syncthreads();

        uint32_t base = sb + cur * STAGE_BYTES;
        #pragma unroll
        for (int ks = 0; ks < 2; ks++) {
            uint32_t koff = (uint32_t)(ks * 32 + (lane >> 4) * 16);  // bytes
            uint32_t ah[2][4], al[2][4];
            #pragma unroll
            for (int mt = 0; mt < 2; mt++) {
                uint32_t r = wm * 32 + mt * 16 + (lane & 15);
                uint32_t addr = base + r * ROW_BYTES + koff;
                ldm_x4(ah[mt], addr);
                ldm_x4(al[mt], addr + TILE_BYTES);
            }
            uint32_t bh[4][4], bl[4][4];
            #pragma unroll
            for (int ng = 0; ng < 4; ng++) {
                uint32_t r = wn * 64 + ng * 16 + (lane & 15);
                uint32_t addr = base + 2 * TILE_BYTES + r * ROW_BYTES + koff;
                ldm_x4(bh[ng], addr);
                ldm_x4(bl[ng], addr + TILE_BYTES);
            }
            #pragma unroll
            for (int mt = 0; mt < 2; mt++)
                #pragma unroll
                for (int ng = 0; ng < 4; ng++) {
                    // n-tile 2*ng uses regs {0,2}; n-tile 2*ng+1 uses {1,3}
                    mma_bf16(acc[mt][2 * ng],     ah[mt], bh[ng][0], bh[ng][2]);
                    mma_bf16(acc[mt][2 * ng],     ah[mt], bl[ng][0], bl[ng][2]);
                    mma_bf16(acc[mt][2 * ng],     al[mt], bh[ng][0], bh[ng][2]);
                    mma_bf16(acc[mt][2 * ng + 1], ah[mt], bh[ng][1], bh[ng][3]);
                    mma_bf16(acc[mt][2 * ng + 1], ah[mt], bl[ng][1], bl[ng][3]);
                    mma_bf16(acc[mt][2 * ng + 1], al[mt], bh[ng][1], bh[ng][3]);
                }
        }
        __syncthreads();
    }

    // epilogue: D m16n8 frag: d0 (r, c), d1 (r, c+1), d2 (r+8, c), d3 (r+8, c+1)
    #pragma unroll
    for (int mt = 0; mt < 2; mt++) {
        int r0 = wm * 32 + mt * 16 + (lane >> 2);
        #pragma unroll
        for (int nt = 0; nt < 8; nt++) {
            int c = wn * 64 + nt * 8 + (lane & 3) * 2;
            float bx = 0.0f, by = 0.0f;
            if (bias) { bx = bias[c]; by = bias[c + 1]; }
            float2 v0 = { acc[mt][nt][0] + bx, acc[mt][nt][1] + by };
            float2 v1 = { acc[mt][nt][2] + bx, acc[mt][nt][3] + by };
            *(float2*)(Out + (size_t)r0 * ldo + c) = v0;
            *(float2*)(Out + (size_t)(r0 + 8) * ldo + c) = v1;
        }
    }
}

// ---------------- GEMM wrappers ----------------
__global__ __launch_bounds__(256)
void k_gemm_nt(const bf16* __restrict__ Ah, const bf16* __restrict__ Al,
               const bf16* __restrict__ Bh, const bf16* __restrict__ Bl,
               const float* __restrict__ bias, float* __restrict__ Out)
{
    size_t bm = (size_t)blockIdx.y * 128;
    size_t bn = (size_t)blockIdx.x * 128;
    gemm_hmma_tile(Ah + bm * NC, Al + bm * NC, NC,
                   Bh + bn * NC, Bl + bn * NC, NC,
                   bias + bn, Out + bm * NC + bn, NC, NC);
}

__global__ __launch_bounds__(256)
void k_gemm_scores()
{
    int bh = blockIdx.z, b = bh >> 4, h = bh & 15;
    size_t bm = (size_t)blockIdx.y * 128;
    size_t bn = (size_t)blockIdx.x * 128;
    size_t arow = ((size_t)b * NS + bm) * NC + (size_t)h * ND;
    size_t brow = ((size_t)b * NS + bn) * NC + (size_t)h * ND;
    float* Out = g_sc + (size_t)bh * NS * NS + bm * NS + bn;
    gemm_hmma_tile(g_qh + arow, g_ql + arow, NC,
                   g_kh + brow, g_kl + brow, NC,
                   nullptr, Out, NS, ND);
}

__global__ __launch_bounds__(256)
void k_gemm_pv()
{
    int bh = blockIdx.z, b = bh >> 4, h = bh & 15;
    size_t bm = (size_t)blockIdx.y * 128;
    size_t arow = (size_t)bh * NS * NS + bm * NS;
    size_t brow = ((size_t)b * NC + (size_t)h * ND) * NS;
    float* Out = g_ctx + ((size_t)b * NS + bm) * NC + (size_t)h * ND;
    gemm_hmma_tile(g_ph + arow, g_pl + arow, NS,
                   g_vth + brow, g_vtl + brow, NS,
                   nullptr, Out, NC, NS);
}

// ---------------- elementwise kernels ----------------
__device__ __forceinline__ void split2(float x, bf16& h, bf16& l) {
    h = __float2bfloat16_rn(x);
    l = __float2bfloat16_rn(x - __bfloat162float(h));
}

__global__ __launch_bounds__(256) void cvt_split(const float* __restrict__ src,
                                                 bf16* __restrict__ hi,
                                                 bf16* __restrict__ lo)
{
    size_t i = (size_t)blockIdx.x * 256 + threadIdx.x;
    float4 v = ((const float4*)src)[i];
    bf16 h0, h1, h2, h3, l0, l1, l2, l3;
    split2(v.x, h0, l0); split2(v.y, h1, l1);
    split2(v.z, h2, l2); split2(v.w, h3, l3);
    __nv_bfloat162* hp = (__nv_bfloat162*)hi;
    __nv_bfloat162* lp = (__nv_bfloat162*)lo;
    hp[2 * i]     = __nv_bfloat162{h0, h1};
    hp[2 * i + 1] = __nv_bfloat162{h2, h3};
    lp[2 * i]     = __nv_bfloat162{l0, l1};
    lp[2 * i + 1] = __nv_bfloat162{l2, l3};
}

// V transpose + split: g_v[(b*S+s), c] -> vT[(b*C+c), s] (hi/lo bf16)
__global__ __launch_bounds__(256) void transpose_split_v()
{
    __shared__ float t[32][33];
    int b = blockIdx.z;
    int s0 = blockIdx.x * 32, c0 = blockIdx.y * 32;
    int tx = threadIdx.x, ty = threadIdx.y;  // 32 x 8
    #pragma unroll
    for (int j = 0; j < 4; j++) {
        int s = s0 + ty + j * 8;
        t[ty + j * 8][tx] = g_v[((size_t)b * NS + s) * NC + c0 + tx];
    }
    __syncthreads();
    #pragma unroll
    for (int j = 0; j < 4; j++) {
        int c = c0 + ty + j * 8;
        float v = t[tx][ty + j * 8];
        bf16 h, l;
        split2(v, h, l);
        size_t o = ((size_t)b * NC + c) * NS + s0 + tx;
        g_vth[o] = h;
        g_vtl[o] = l;
    }
}

// Per-head RMSNorm + RoPE; reads fp32 g_q/g_k, writes split bf16 qh/ql/kh/kl.
__global__ __launch_bounds__(256) void rmsnorm_rope(
    const float* __restrict__ rope,
    const float* __restrict__ gq, const float* __restrict__ gk)
{
    int warp = blockIdx.x * 8 + (threadIdx.x >> 5);
    int lane = threadIdx.x & 31;
    int m = warp >> 4;
    int h = warp & 15;
    int s = m & (NS - 1);

    size_t off = (size_t)m * NC + h * ND;
    const float* qr = g_q + off;
    const float* kr = g_k + off;
    const float* rp = rope + (size_t)s * (ND / 2) * 4;
    int d = lane * 4;

    float4 xq = *(const float4*)(qr + d);
    float4 xk = *(const float4*)(kr + d);
    float ssq = xq.x * xq.x + xq.y * xq.y + xq.z * xq.z + xq.w * xq.w;
    float ssk = xk.x * xk.x + xk.y * xk.y + xk.z * xk.z + xk.w * xk.w;
    #pragma unroll
    for (int o = 16; o; o >>= 1) {
        ssq += __shfl_xor_sync(0xffffffffu, ssq, o);
        ssk += __shfl_xor_sync(0xffffffffu, ssk, o);
    }
    float rq = rsqrtf(ssq * (1.0f / ND) + RMS_EPS);
    float rk = rsqrtf(ssk * (1.0f / ND) + RMS_EPS);

    float4 gqv = *(const float4*)(gq + d);
    float4 gkv = *(const float4*)(gk + d);
    xq.x *= rq * gqv.x; xq.y *= rq * gqv.y; xq.z *= rq * gqv.z; xq.w *= rq * gqv.w;
    xk.x *= rk * gkv.x; xk.y *= rk * gkv.y; xk.z *= rk * gkv.z; xk.w *= rk * gkv.w;

    float4 r0 = *(const float4*)(rp + (size_t)(2 * lane) * 4);
    float4 r1 = *(const float4*)(rp + (size_t)(2 * lane + 1) * 4);
    float4 oq, ok;
    oq.x = r0.x * xq.x + r0.y * xq.y;  oq.y = r0.z * xq.x + r0.w * xq.y;
    oq.z = r1.x * xq.z + r1.y * xq.w;  oq.w = r1.z * xq.z + r1.w * xq.w;
    ok.x = r0.x * xk.x + r0.y * xk.y;  ok.y = r0.z * xk.x + r0.w * xk.y;
    ok.z = r1.x * xk.z + r1.y * xk.w;  ok.w = r1.z * xk.z + r1.w * xk.w;

    bf16 h0, h1, h2, h3, l0, l1, l2, l3;
    split2(oq.x, h0, l0); split2(oq.y, h1, l1);
    split2(oq.z, h2, l2); split2(oq.w, h3, l3);
    *(__nv_bfloat162*)(g_qh + off + d)     = __nv_bfloat162{h0, h1};
    *(__nv_bfloat162*)(g_qh + off + d + 2) = __nv_bfloat162{h2, h3};
    *(__nv_bfloat162*)(g_ql + off + d)     = __nv_bfloat162{l0, l1};
    *(__nv_bfloat162*)(g_ql + off + d + 2) = __nv_bfloat162{l2, l3};

    split2(ok.x, h0, l0); split2(ok.y, h1, l1);
    split2(ok.z, h2, l2); split2(ok.w, h3, l3);
    *(__nv_bfloat162*)(g_kh + off + d)     = __nv_bfloat162{h0, h1};
    *(__nv_bfloat162*)(g_kh + off + d + 2) = __nv_bfloat162{h2, h3};
    *(__nv_bfloat162*)(g_kl + off + d)     = __nv_bfloat162{l0, l1};
    *(__nv_bfloat162*)(g_kl + off + d + 2) = __nv_bfloat162{l2, l3};
}

// Row softmax over 2048 keys; reads fp32 scores, writes split bf16 probs.
__global__ __launch_bounds__(256) void softmax_rows()
{
    const float* p = g_sc + (size_t)blockIdx.x * NS;
    bf16* ph = g_ph + (size_t)blockIdx.x * NS;
    bf16* pl = g_pl + (size_t)blockIdx.x * NS;
    int tid = threadIdx.x;
    __shared__ float sh[8];

    float4 v0 = ((const float4*)p)[tid];
    float4 v1 = ((const float4*)p)[tid + 256];
    float mx = fmaxf(fmaxf(fmaxf(v0.x, v0.y), fmaxf(v0.z, v0.w)),
                     fmaxf(fmaxf(v1.x, v1.y), fmaxf(v1.z, v1.w)));
    #pragma unroll
    for (int o = 16; o; o >>= 1) mx = fmaxf(mx, __shfl_xor_sync(0xffffffffu, mx, o));
    if ((tid & 31) == 0) sh[tid >> 5] = mx;
    __syncthreads();
    if (tid < 32) {
        float t = sh[tid & 7];
        #pragma unroll
        for (int o = 4; o; o >>= 1) t = fmaxf(t, __shfl_xor_sync(0xffffffffu, t, o));
        if (tid == 0) sh[0] = t;
    }
    __syncthreads();
    mx = sh[0];
    __syncthreads();

    v0.x = __expf((v0.x - mx) * SM_SCALE); v0.y = __expf((v0.y - mx) * SM_SCALE);
    v0.z = __expf((v0.z - mx) * SM_SCALE); v0.w = __expf((v0.w - mx) * SM_SCALE);
    v1.x = __expf((v1.x - mx) * SM_SCALE); v1.y = __expf((v1.y - mx) * SM_SCALE);
    v1.z = __expf((v1.z - mx) * SM_SCALE); v1.w = __expf((v1.w - mx) * SM_SCALE);
    float sum = v0.x + v0.y + v0.z + v0.w + v1.x + v1.y + v1.z + v1.w;
    #pragma unroll
    for (int o = 16; o; o >>= 1) sum += __shfl_xor_sync(0xffffffffu, sum, o);
    if ((tid & 31) == 0) sh[tid >> 5] = sum;
    __syncthreads();
    if (tid < 32) {
        float t = sh[tid & 7];
        #pragma unroll
        for (int o = 4; o; o >>= 1) t += __shfl_xor_sync(0xffffffffu, t, o);
        if (tid == 0) sh[0] = t;
    }
    __syncthreads();
    float inv = 1.0f / sh[0];
    v0.x *= inv; v0.y *= inv; v0.z *= inv; v0.w *= inv;
    v1.x *= inv; v1.y *= inv; v1.z *= inv; v1.w *= inv;

    bf16 h0, h1, h2, h3, l0, l1, l2, l3;
    split2(v0.x, h0, l0); split2(v0.y, h1, l1);
    split2(v0.z, h2, l2); split2(v0.w, h3, l3);
    *(__nv_bfloat162*)(ph + tid * 4)     = __nv_bfloat162{h0, h1};
    *(__nv_bfloat162*)(ph + tid * 4 + 2) = __nv_bfloat162{h2, h3};
    *(__nv_bfloat162*)(pl + tid * 4)     = __nv_bfloat162{l0, l1};
    *(__nv_bfloat162*)(pl + tid * 4 + 2) = __nv_bfloat162{l2, l3};

    split2(v1.x, h0, l0); split2(v1.y, h1, l1);
    split2(v1.z, h2, l2); split2(v1.w, h3, l3);
    *(__nv_bfloat162*)(ph + (tid + 256) * 4)     = __nv_bfloat162{h0, h1};
    *(__nv_bfloat162*)(ph + (tid + 256) * 4 + 2) = __nv_bfloat162{h2, h3};
    *(__nv_bfloat162*)(pl + (tid + 256) * 4)     = __nv_bfloat162{l0, l1};
    *(__nv_bfloat162*)(pl + (tid + 256) * 4 + 2) = __nv_bfloat162{l2, l3};
}

// ---------------- launch ----------------
extern "C" void kernel_launch(void* const* d_in, const int* in_sizes, int n_in,
                              void* d_out, int out_size)
{
    const float* x    = (const float*)d_in[0];
    const float* rope = (const float*)d_in[1];
    const float* Wq   = (const float*)d_in[2];
    const float* bq   = (const float*)d_in[3];
    const float* Wk   = (const float*)d_in[4];
    const float* bk   = (const float*)d_in[5];
    const float* Wv   = (const float*)d_in[6];
    const float* bv   = (const float*)d_in[7];
    const float* gq   = (const float*)d_in[8];
    const float* gk   = (const float*)d_in[9];
    const float* Wo   = (const float*)d_in[10];
    const float* bo   = (const float*)d_in[11];
    float* out = (float*)d_out;

    cudaFuncSetAttribute(k_gemm_nt, cudaFuncAttributeMaxDynamicSharedMemorySize, GEMM_SMEM);
    cudaFuncSetAttribute(k_gemm_scores, cudaFuncAttributeMaxDynamicSharedMemorySize, GEMM_SMEM);
    cudaFuncSetAttribute(k_gemm_pv, cudaFuncAttributeMaxDynamicSharedMemorySize, GEMM_SMEM);

    float *qp, *kp, *vp, *ctxp;
    bf16 *xh, *xl, *wqh, *wql, *wkh, *wkl, *wvh, *wvl, *woh, *wol, *ch, *cl;
    cudaGetSymbolAddress((void**)&qp, g_q);
    cudaGetSymbolAddress((void**)&kp, g_k);
    cudaGetSymbolAddress((void**)&vp, g_v);
    cudaGetSymbolAddress((void**)&ctxp, g_ctx);
    cudaGetSymbolAddress((void**)&xh, g_xh);   cudaGetSymbolAddress((void**)&xl, g_xl);
    cudaGetSymbolAddress((void**)&wqh, g_wqh); cudaGetSymbolAddress((void**)&wql, g_wql);
    cudaGetSymbolAddress((void**)&wkh, g_wkh); cudaGetSymbolAddress((void**)&wkl, g_wkl);
    cudaGetSymbolAddress((void**)&wvh, g_wvh); cudaGetSymbolAddress((void**)&wvl, g_wvl);
    cudaGetSymbolAddress((void**)&woh, g_woh); cudaGetSymbolAddress((void**)&wol, g_wol);
    cudaGetSymbolAddress((void**)&ch, g_ch);   cudaGetSymbolAddress((void**)&cl, g_cl);

    const size_t nX = (size_t)NM * NC;       // 8M elems
    const size_t nW = (size_t)NC * NC;       // 4M elems

    cvt_split<<<(unsigned)(nX / 1024), 256>>>(x, xh, xl);
    cvt_split<<<(unsigned)(nW / 1024), 256>>>(Wq, wqh, wql);
    cvt_split<<<(unsigned)(nW / 1024), 256>>>(Wk, wkh, wkl);
    cvt_split<<<(unsigned)(nW / 1024), 256>>>(Wv, wvh, wvl);
    cvt_split<<<(unsigned)(nW / 1024), 256>>>(Wo, woh, wol);

    dim3 gProj(NC / 128, NM / 128);          // (16, 32)
    k_gemm_nt<<<gProj, 256, GEMM_SMEM>>>(xh, xl, wqh, wql, bq, qp);
    k_gemm_nt<<<gProj, 256, GEMM_SMEM>>>(xh, xl, wkh, wkl, bk, kp);
    k_gemm_nt<<<gProj, 256, GEMM_SMEM>>>(xh, xl, wvh, wvl, bv, vp);

    rmsnorm_rope<<<(NM * NH) / 8, 256>>>(rope, gq, gk);
    transpose_split_v<<<dim3(NS / 32, NC / 32, NB), dim3(32, 8)>>>();

    k_gemm_scores<<<dim3(NS / 128, NS / 128, NBH), 256, GEMM_SMEM>>>();
    softmax_rows<<<NBH * NS, 256>>>();
    k_gemm_pv<<<dim3(1, NS / 128, NBH), 256, GEMM_SMEM>>>();

    cvt_split<<<(unsigned)(nX / 1024), 256>>>(ctxp, ch, cl);
    k_gemm_nt<<<gProj, 256, GEMM_SMEM>>>(ch, cl, woh, wol, bo, out);
}